// round 10
// baseline (speedup 1.0000x reference)
#include <cuda_runtime.h>
#include <math.h>
#include <stdint.h>

// Problem constants
#define BB   4
#define LL   2048
#define DD   512
#define HH   8
#define HD   64
#define DFF  2048
#define MR   (BB*LL)   // 8192 rows

// ---------------- scratch (device globals: allocation-free) ----------------
__device__ float g_qkv [MR * 3 * DD];
__device__ float g_vals[MR * DD];
__device__ float g_tmp [MR * DD];
__device__ float g_x1  [MR * DD];
__device__ float g_ff  [MR * DFF];
__device__ int   g_mflag[16 * 32];   // per (128-row qtile, 64-col stile) all-ones flag

// ---------------------------------------------------------------------------
// tf32 helpers (legacy mma.sync path — supported on base sm_100)
// ---------------------------------------------------------------------------
__device__ __forceinline__ uint32_t f2tf32(float x) {
    uint32_t r;
    asm("cvt.rna.tf32.f32 %0, %1;" : "=r"(r) : "f"(x));
    return r;
}

#define MMA_TF32(d, a, b)                                                      \
    asm volatile("mma.sync.aligned.m16n8k8.row.col.f32.tf32.tf32.f32 "         \
        "{%0,%1,%2,%3}, {%4,%5,%6,%7}, {%8,%9}, {%0,%1,%2,%3};"                \
        : "+f"((d)[0]), "+f"((d)[1]), "+f"((d)[2]), "+f"((d)[3])               \
        : "r"((a)[0]), "r"((a)[1]), "r"((a)[2]), "r"((a)[3]),                  \
          "r"((b)[0]), "r"((b)[1]))

// ---------------------------------------------------------------------------
// mma.sync tf32 GEMM (unchanged — proven).
// ---------------------------------------------------------------------------
#define SPAD 24
#define GEMM_SMEM (2 * 2 * 128 * SPAD * 4)   // 49152 bytes

template<int RELU>
__global__ __launch_bounds__(256, 2)
void mma_gemm(const float* __restrict__ A, const float* __restrict__ W,
              const float* __restrict__ bias, float* __restrict__ C,
              int M, int N, int K)
{
    extern __shared__ float gsm[];
    float* As = gsm;
    float* Bs = gsm + 2 * 128 * SPAD;

    const int tid  = threadIdx.x;
    const int wid  = tid >> 5, lane = tid & 31;
    const int grp  = lane >> 2, qd = lane & 3;
    const int wm   = (wid & 1) * 64;
    const int wn   = (wid >> 1) * 32;
    const int bm   = blockIdx.y * 128;
    const int bn   = blockIdx.x * 128;

    const int lrow = tid >> 1;
    const int lk8  = (tid & 1) * 8;

    const float* Ap = A + (size_t)(bm + lrow) * K + lk8;
    const float* Wp = W + (size_t)(bn + lrow) * K + lk8;

    float acc[4][4][4];
    #pragma unroll
    for (int i = 0; i < 4; i++)
        #pragma unroll
        for (int j = 0; j < 4; j++)
            #pragma unroll
            for (int r = 0; r < 4; r++) acc[i][j][r] = 0.f;

    float4 ra0 = *(const float4*)(Ap);
    float4 ra1 = *(const float4*)(Ap + 4);
    float4 rb0 = *(const float4*)(Wp);
    float4 rb1 = *(const float4*)(Wp + 4);

    auto store_stage = [&](int bf) {
        uint32_t* pa = (uint32_t*)&As[bf * 128 * SPAD + lrow * SPAD + lk8];
        uint32_t* pb = (uint32_t*)&Bs[bf * 128 * SPAD + lrow * SPAD + lk8];
        pa[0] = f2tf32(ra0.x); pa[1] = f2tf32(ra1.x); pa[2] = f2tf32(ra0.y); pa[3] = f2tf32(ra1.y);
        pa[4] = f2tf32(ra0.z); pa[5] = f2tf32(ra1.z); pa[6] = f2tf32(ra0.w); pa[7] = f2tf32(ra1.w);
        pb[0] = f2tf32(rb0.x); pb[1] = f2tf32(rb1.x); pb[2] = f2tf32(rb0.y); pb[3] = f2tf32(rb1.y);
        pb[4] = f2tf32(rb0.z); pb[5] = f2tf32(rb1.z); pb[6] = f2tf32(rb0.w); pb[7] = f2tf32(rb1.w);
    };

    store_stage(0);
    __syncthreads();

    const int NS = K >> 4;
    for (int s = 0; s < NS; ++s) {
        const int p = s & 1;
        if (s + 1 < NS) {
            const float* An = Ap + (size_t)(s + 1) * 16;
            const float* Wn = Wp + (size_t)(s + 1) * 16;
            ra0 = *(const float4*)(An);
            ra1 = *(const float4*)(An + 4);
            rb0 = *(const float4*)(Wn);
            rb1 = *(const float4*)(Wn + 4);
        }
        const float* Ab = &As[p * 128 * SPAD];
        const float* Bb = &Bs[p * 128 * SPAD];
        #pragma unroll
        for (int ks = 0; ks < 2; ++ks) {
            const int kb = ks * 8;
            uint32_t af[4][4], bf[4][2];
            #pragma unroll
            for (int mt = 0; mt < 4; ++mt) {
                const int r = wm + mt * 16 + grp;
                uint2 a02 = *(const uint2*)&Ab[r * SPAD + kb + 2 * qd];
                uint2 a13 = *(const uint2*)&Ab[(r + 8) * SPAD + kb + 2 * qd];
                af[mt][0] = a02.x; af[mt][1] = a13.x;
                af[mt][2] = a02.y; af[mt][3] = a13.y;
            }
            #pragma unroll
            for (int nt = 0; nt < 4; ++nt) {
                const int n = wn + nt * 8 + grp;
                uint2 b01 = *(const uint2*)&Bb[n * SPAD + kb + 2 * qd];
                bf[nt][0] = b01.x; bf[nt][1] = b01.y;
            }
            #pragma unroll
            for (int mt = 0; mt < 4; ++mt)
                #pragma unroll
                for (int nt = 0; nt < 4; ++nt)
                    MMA_TF32(acc[mt][nt], af[mt], bf[nt]);
        }
        if (s + 1 < NS) store_stage(p ^ 1);
        __syncthreads();
    }

    #pragma unroll
    for (int mt = 0; mt < 4; ++mt) {
        const int row = bm + wm + mt * 16 + grp;
        #pragma unroll
        for (int nt = 0; nt < 4; ++nt) {
            const int col = bn + wn + nt * 8 + 2 * qd;
            const float2 bv = *(const float2*)&bias[col];
            float2 o0, o1;
            o0.x = acc[mt][nt][0] + bv.x; o0.y = acc[mt][nt][1] + bv.y;
            o1.x = acc[mt][nt][2] + bv.x; o1.y = acc[mt][nt][3] + bv.y;
            if (RELU) {
                o0.x = fmaxf(o0.x, 0.f); o0.y = fmaxf(o0.y, 0.f);
                o1.x = fmaxf(o1.x, 0.f); o1.y = fmaxf(o1.y, 0.f);
            }
            *(float2*)(C + (size_t)row * N + col)       = o0;
            *(float2*)(C + (size_t)(row + 8) * N + col) = o1;
        }
    }
}

// ---------------------------------------------------------------------------
// mask tile flags (unchanged).
// ---------------------------------------------------------------------------
__global__ __launch_bounds__(256)
void mask_flags(const int* __restrict__ mask, int* __restrict__ flags)
{
    const int idx = blockIdx.x;
    const int qt = idx >> 5, st = idx & 31;
    const int tid = threadIdx.x;
    int ok = 1;
    for (int i = tid; i < 128 * 64; i += 256) {
        int r = qt * 128 + (i >> 6);
        int c = st * 64 + (i & 63);
        ok &= (mask[(size_t)r * LL + c] != 0);
    }
    int all = __syncthreads_and(ok);
    if (tid == 0) flags[idx] = all;
}

// ---------------------------------------------------------------------------
// Flash attention: mma.sync tf32, register-prefetch double buffering,
// ONE __syncthreads per tile.
//  iter st: [issue LDG st+1] -> QKT(cur) -> softmax -> PV(cur)
//           -> STS staged tile into buf cur^1 -> barrier.
// Buf cur^1 was freed by the end-of-(st-1) barrier, so pre-barrier writes
// are race-free. K/V stored raw fp32 (tf32 MMA truncates; R8-validated).
// Q rna-rounded+scaled+k-interleaved (LDS.64 A-frags). exp2 softmax.
// Forced 2 CTAs/SM via launch bounds.
// ---------------------------------------------------------------------------
#define QST 72
#define KST 68
#define VST 72
#define ATT_SMEM ((128 * QST + 2 * 64 * KST + 2 * 64 * VST) * 4)   // 108544 B

__global__ __launch_bounds__(256, 2)
void flash_attn_mma(const float* __restrict__ qkv, const int* __restrict__ mask,
                    const int* __restrict__ flags, float* __restrict__ vals)
{
    extern __shared__ float sm[];
    float* Qs  = sm;                       // [128][QST] tf32, scaled, k-interleaved
    float* Kb0 = sm + 128 * QST;           // raw fp32 [64][KST]
    float* Kb1 = Kb0 + 64 * KST;
    float* Vb0 = Kb1 + 64 * KST;           // raw fp32 [64][VST]
    float* Vb1 = Vb0 + 64 * VST;
    float* Kb[2] = { Kb0, Kb1 };
    float* Vb[2] = { Vb0, Vb1 };

    const int tid  = threadIdx.x;
    const int wid  = tid >> 5, lane = tid & 31;
    const int grp  = lane >> 2, qd = lane & 3;
    const int qt   = blockIdx.x;
    const int head = blockIdx.y;
    const int b    = blockIdx.z;
    const int qbase = qt * 128;
    const int m0   = wid * 16;

    const float QSCALE = 0.125f * 1.44269504088896340736f;   // (1/8)*log2(e)

    // ---- Q tile: rna + scale + k-interleave ----
    const float* qp = qkv + ((size_t)(b * LL + qbase)) * (3 * DD) + head * (3 * HD);
    for (int s = tid; s < 128 * 16; s += 256) {
        int r = s >> 4, c = (s & 15) * 4;
        float4 v = *(const float4*)(qp + (size_t)r * (3 * DD) + c);
        const int kb = c & ~7, h = (c >> 2) & 1;
        uint32_t* row = (uint32_t*)&Qs[r * QST + kb + h];
        row[0] = f2tf32(v.x * QSCALE); row[2] = f2tf32(v.y * QSCALE);
        row[4] = f2tf32(v.z * QSCALE); row[6] = f2tf32(v.w * QSCALE);
    }

    // ---- tile 0 -> buffer 0 (synchronous, raw) ----
    const float* kvbase = qkv + ((size_t)(b * LL)) * (3 * DD) + head * (3 * HD) + HD;
    for (int s = tid; s < 64 * 16; s += 256) {
        int r = s >> 4, c = (s & 15) * 4;
        const float* kp = kvbase + (size_t)r * (3 * DD) + c;
        *(float4*)&Kb0[r * KST + c] = *(const float4*)(kp);
        *(float4*)&Vb0[r * VST + c] = *(const float4*)(kp + HD);
    }
    __syncthreads();                       // publish Q + tile 0

    const int lr = tid >> 2;               // 0..63 staging row
    const int lc = (tid & 3) * 16;         // staging col base

    float o[8][4];
    #pragma unroll
    for (int nt = 0; nt < 8; ++nt)
        #pragma unroll
        for (int r = 0; r < 4; ++r) o[nt][r] = 0.f;
    float m_0 = -INFINITY, m_1 = -INFINITY, l_0 = 0.f, l_1 = 0.f;

    const int NT = LL / 64;
    for (int st = 0; st < NT; ++st) {
        const int cur = st & 1;
        const float* Ks = Kb[cur];
        const float* Vs = Vb[cur];
        const int sbase = st * 64;

        // ---- issue prefetch LDGs for tile st+1 (latency hidden by body) ----
        float4 kst[4], vst[4];
        if (st + 1 < NT) {
            const float* kp = kvbase + (size_t)((st + 1) * 64 + lr) * (3 * DD) + lc;
            #pragma unroll
            for (int i = 0; i < 4; ++i) {
                kst[i] = *(const float4*)(kp + i * 4);
                vst[i] = *(const float4*)(kp + HD + i * 4);
            }
        }

        // ---- S' = Qs @ K^T ----
        float sacc[8][4];
        #pragma unroll
        for (int nt = 0; nt < 8; ++nt)
            #pragma unroll
            for (int r = 0; r < 4; ++r) sacc[nt][r] = 0.f;

        #pragma unroll
        for (int ks = 0; ks < 8; ++ks) {
            const int k0 = ks * 8;
            uint32_t a[4];
            {
                uint2 a02 = *(const uint2*)&Qs[(m0 + grp    ) * QST + k0 + 2 * qd];
                uint2 a13 = *(const uint2*)&Qs[(m0 + grp + 8) * QST + k0 + 2 * qd];
                a[0] = a02.x; a[1] = a13.x; a[2] = a02.y; a[3] = a13.y;
            }
            #pragma unroll
            for (int nt = 0; nt < 8; ++nt) {
                uint32_t bb[2];
                bb[0] = __float_as_uint(Ks[(nt * 8 + grp) * KST + k0 + qd]);
                bb[1] = __float_as_uint(Ks[(nt * 8 + grp) * KST + k0 + qd + 4]);
                MMA_TF32(sacc[nt], a, bb);
            }
        }

        // ---- mask (slow path only when tile has zeros) ----
        if (flags[qt * 32 + st] == 0) {
            const int r0g = qbase + m0 + grp, r1g = r0g + 8;
            #pragma unroll
            for (int nt = 0; nt < 8; ++nt) {
                const int c0 = sbase + nt * 8 + 2 * qd;
                if (mask[(size_t)r0g * LL + c0    ] == 0) sacc[nt][0] = -INFINITY;
                if (mask[(size_t)r0g * LL + c0 + 1] == 0) sacc[nt][1] = -INFINITY;
                if (mask[(size_t)r1g * LL + c0    ] == 0) sacc[nt][2] = -INFINITY;
                if (mask[(size_t)r1g * LL + c0 + 1] == 0) sacc[nt][3] = -INFINITY;
            }
        }

        // ---- online softmax in exp2 domain ----
        float rm0 = -INFINITY, rm1 = -INFINITY;
        #pragma unroll
        for (int nt = 0; nt < 8; ++nt) {
            rm0 = fmaxf(rm0, fmaxf(sacc[nt][0], sacc[nt][1]));
            rm1 = fmaxf(rm1, fmaxf(sacc[nt][2], sacc[nt][3]));
        }
        rm0 = fmaxf(rm0, __shfl_xor_sync(0xffffffffu, rm0, 1));
        rm0 = fmaxf(rm0, __shfl_xor_sync(0xffffffffu, rm0, 2));
        rm1 = fmaxf(rm1, __shfl_xor_sync(0xffffffffu, rm1, 1));
        rm1 = fmaxf(rm1, __shfl_xor_sync(0xffffffffu, rm1, 2));
        const float mn0 = fmaxf(m_0, rm0), mn1 = fmaxf(m_1, rm1);
        const float al0 = exp2f(m_0 - mn0), al1 = exp2f(m_1 - mn1);
        m_0 = mn0; m_1 = mn1;

        float s0 = 0.f, s1 = 0.f;
        #pragma unroll
        for (int nt = 0; nt < 8; ++nt) {
            float p0 = __uint_as_float(f2tf32(exp2f(sacc[nt][0] - mn0)));
            float p1 = __uint_as_float(f2tf32(exp2f(sacc[nt][1] - mn0)));
            float p2 = __uint_as_float(f2tf32(exp2f(sacc[nt][2] - mn1)));
            float p3 = __uint_as_float(f2tf32(exp2f(sacc[nt][3] - mn1)));
            sacc[nt][0] = p0; sacc[nt][1] = p1; sacc[nt][2] = p2; sacc[nt][3] = p3;
            s0 += p0 + p1; s1 += p2 + p3;
        }
        s0 += __shfl_xor_sync(0xffffffffu, s0, 1);
        s0 += __shfl_xor_sync(0xffffffffu, s0, 2);
        s1 += __shfl_xor_sync(0xffffffffu, s1, 1);
        s1 += __shfl_xor_sync(0xffffffffu, s1, 2);
        l_0 = l_0 * al0 + s0;
        l_1 = l_1 * al1 + s1;
        #pragma unroll
        for (int nt = 0; nt < 8; ++nt) {
            o[nt][0] *= al0; o[nt][1] *= al0;
            o[nt][2] *= al1; o[nt][3] *= al1;
        }

        // ---- O += P @ V  (A-frag via intra-quad shfl; V raw -> truncation) ----
        const int srl = (lane & ~3) | (qd >> 1);
        #pragma unroll
        for (int ks = 0; ks < 8; ++ks) {
            uint32_t a[4];
            {
                float t0 = __shfl_sync(0xffffffffu, sacc[ks][0], srl);
                float t1 = __shfl_sync(0xffffffffu, sacc[ks][1], srl);
                float u0 = __shfl_sync(0xffffffffu, sacc[ks][0], srl + 2);
                float u1 = __shfl_sync(0xffffffffu, sacc[ks][1], srl + 2);
                a[0] = __float_as_uint((qd & 1) ? t1 : t0);
                a[2] = __float_as_uint((qd & 1) ? u1 : u0);
                t0 = __shfl_sync(0xffffffffu, sacc[ks][2], srl);
                t1 = __shfl_sync(0xffffffffu, sacc[ks][3], srl);
                u0 = __shfl_sync(0xffffffffu, sacc[ks][2], srl + 2);
                u1 = __shfl_sync(0xffffffffu, sacc[ks][3], srl + 2);
                a[1] = __float_as_uint((qd & 1) ? t1 : t0);
                a[3] = __float_as_uint((qd & 1) ? u1 : u0);
            }
            const int k0 = ks * 8;
            #pragma unroll
            for (int nt = 0; nt < 8; ++nt) {
                uint32_t bb[2];
                bb[0] = __float_as_uint(Vs[(k0 + qd    ) * VST + nt * 8 + grp]);
                bb[1] = __float_as_uint(Vs[(k0 + qd + 4) * VST + nt * 8 + grp]);
                MMA_TF32(o[nt], a, bb);
            }
        }

        // ---- drain staged tile into the other buffer, single barrier ----
        if (st + 1 < NT) {
            float* kd = &Kb[cur ^ 1][lr * KST + lc];
            float* vd = &Vb[cur ^ 1][lr * VST + lc];
            #pragma unroll
            for (int i = 0; i < 4; ++i) {
                *(float4*)(kd + i * 4) = kst[i];
                *(float4*)(vd + i * 4) = vst[i];
            }
        }
        __syncthreads();
    }

    // ---- normalize + write (head-concat [B,L,D]) ----
    const float li0 = 1.f / l_0, li1 = 1.f / l_1;
    const int r0g = qbase + m0 + grp;
    #pragma unroll
    for (int nt = 0; nt < 8; ++nt) {
        const int col = head * HD + nt * 8 + 2 * qd;
        float2 w0 = make_float2(o[nt][0] * li0, o[nt][1] * li0);
        float2 w1 = make_float2(o[nt][2] * li1, o[nt][3] * li1);
        *(float2*)&vals[((size_t)(b * LL + r0g    )) * DD + col] = w0;
        *(float2*)&vals[((size_t)(b * LL + r0g + 8)) * DD + col] = w1;
    }
}

// ---------------------------------------------------------------------------
// Fused residual-add + LayerNorm (unchanged).
// ---------------------------------------------------------------------------
__global__ __launch_bounds__(128)
void add_ln(const float* __restrict__ a, const float* __restrict__ bres,
            const float* __restrict__ g, const float* __restrict__ beta,
            float* __restrict__ out)
{
    const int row = blockIdx.x;
    const int tid = threadIdx.x;

    float4 av = ((const float4*)(a    + (size_t)row * DD))[tid];
    float4 bv = ((const float4*)(bres + (size_t)row * DD))[tid];
    float4 x = make_float4(av.x+bv.x, av.y+bv.y, av.z+bv.z, av.w+bv.w);

    float s  = x.x + x.y + x.z + x.w;
    float ss = x.x*x.x + x.y*x.y + x.z*x.z + x.w*x.w;

    #pragma unroll
    for (int o = 16; o > 0; o >>= 1) {
        s  += __shfl_xor_sync(0xffffffffu, s,  o);
        ss += __shfl_xor_sync(0xffffffffu, ss, o);
    }
    __shared__ float red[2][4];
    const int w = tid >> 5, l = tid & 31;
    if (l == 0) { red[0][w] = s; red[1][w] = ss; }
    __syncthreads();
    s  = red[0][0] + red[0][1] + red[0][2] + red[0][3];
    ss = red[1][0] + red[1][1] + red[1][2] + red[1][3];

    const float mean = s * (1.f / DD);
    const float var  = ss * (1.f / DD) - mean * mean;
    const float rstd = rsqrtf(var + 1e-5f);

    float4 gv = ((const float4*)g)[tid];
    float4 ev = ((const float4*)beta)[tid];
    float4 o;
    o.x = (x.x - mean) * rstd * gv.x + ev.x;
    o.y = (x.y - mean) * rstd * gv.y + ev.y;
    o.z = (x.z - mean) * rstd * gv.z + ev.z;
    o.w = (x.w - mean) * rstd * gv.w + ev.w;
    ((float4*)(out + (size_t)row * DD))[tid] = o;
}

// ---------------------------------------------------------------------------
extern "C" void kernel_launch(void* const* d_in, const int* in_sizes, int n_in,
                              void* d_out, int out_size)
{
    const float* src    = (const float*)d_in[0];
    const int*   mask   = (const int*)  d_in[1];
    const float* qkv_w  = (const float*)d_in[2];
    const float* qkv_b  = (const float*)d_in[3];
    const float* out_w  = (const float*)d_in[4];
    const float* out_b  = (const float*)d_in[5];
    const float* w1     = (const float*)d_in[6];
    const float* b1     = (const float*)d_in[7];
    const float* w2     = (const float*)d_in[8];
    const float* b2     = (const float*)d_in[9];
    const float* g1     = (const float*)d_in[10];
    const float* beta1  = (const float*)d_in[11];
    const float* g2     = (const float*)d_in[12];
    const float* beta2  = (const float*)d_in[13];
    float* out = (float*)d_out;

    void* p;
    cudaGetSymbolAddress(&p, g_qkv);   float* qkv   = (float*)p;
    cudaGetSymbolAddress(&p, g_vals);  float* vals  = (float*)p;
    cudaGetSymbolAddress(&p, g_tmp);   float* tmp   = (float*)p;
    cudaGetSymbolAddress(&p, g_x1);    float* x1    = (float*)p;
    cudaGetSymbolAddress(&p, g_ff);    float* ff    = (float*)p;
    cudaGetSymbolAddress(&p, g_mflag); int*   mflag = (int*)p;

    cudaFuncSetAttribute(mma_gemm<0>, cudaFuncAttributeMaxDynamicSharedMemorySize, GEMM_SMEM);
    cudaFuncSetAttribute(mma_gemm<1>, cudaFuncAttributeMaxDynamicSharedMemorySize, GEMM_SMEM);
    cudaFuncSetAttribute(flash_attn_mma, cudaFuncAttributeMaxDynamicSharedMemorySize, ATT_SMEM);

    // 0) mask tile flags
    mask_flags<<<512, 256>>>(mask, mflag);

    // 1) QKV projection
    mma_gemm<0><<<dim3((3*DD)/128, MR/128), 256, GEMM_SMEM>>>(src, qkv_w, qkv_b, qkv, MR, 3*DD, DD);

    // 2) flash attention
    flash_attn_mma<<<dim3(LL/128, HH, BB), 256, ATT_SMEM>>>(qkv, mask, mflag, vals);

    // 3) output projection
    mma_gemm<0><<<dim3(DD/128, MR/128), 256, GEMM_SMEM>>>(vals, out_w, out_b, tmp, MR, DD, DD);

    // 4) x1 = LN(src + proj)
    add_ln<<<MR, 128>>>(src, tmp, g1, beta1, x1);

    // 5) FFN1 + ReLU
    mma_gemm<1><<<dim3(DFF/128, MR/128), 256, GEMM_SMEM>>>(x1, w1, b1, ff, MR, DFF, DD);

    // 6) FFN2
    mma_gemm<0><<<dim3(DD/128, MR/128), 256, GEMM_SMEM>>>(ff, w2, b2, tmp, MR, DD, DFF);

    // 7) out = LN(x1 + ffn2)
    add_ln<<<MR, 128>>>(x1, tmp, g2, beta2, out);
}

// round 11
// speedup vs baseline: 1.1995x; 1.1995x over previous
#include <cuda_runtime.h>
#include <math.h>
#include <stdint.h>

// Problem constants
#define BB   4
#define LL   2048
#define DD   512
#define HH   8
#define HD   64
#define DFF  2048
#define MR   (BB*LL)   // 8192 rows

// ---------------- scratch (device globals: allocation-free) ----------------
__device__ float g_qkv [MR * 3 * DD];
__device__ float g_vals[MR * DD];
__device__ float g_tmp [MR * DD];
__device__ float g_x1  [MR * DD];
__device__ float g_ff  [MR * DFF];
__device__ int   g_mflag[16 * 32];   // per (128-row qtile, 64-col stile) all-ones flag

// ---------------------------------------------------------------------------
// tf32 + async helpers (supported on base sm_100)
// ---------------------------------------------------------------------------
__device__ __forceinline__ uint32_t f2tf32(float x) {
    uint32_t r;
    asm("cvt.rna.tf32.f32 %0, %1;" : "=r"(r) : "f"(x));
    return r;
}
__device__ __forceinline__ uint32_t smem_u32(const void* p) {
    uint32_t a;
    asm("{ .reg .u64 t; cvta.to.shared.u64 t, %1; cvt.u32.u64 %0, t; }"
        : "=r"(a) : "l"(p));
    return a;
}

#define MMA_TF32(d, a, b)                                                      \
    asm volatile("mma.sync.aligned.m16n8k8.row.col.f32.tf32.tf32.f32 "         \
        "{%0,%1,%2,%3}, {%4,%5,%6,%7}, {%8,%9}, {%0,%1,%2,%3};"                \
        : "+f"((d)[0]), "+f"((d)[1]), "+f"((d)[2]), "+f"((d)[3])               \
        : "r"((a)[0]), "r"((a)[1]), "r"((a)[2]), "r"((a)[3]),                  \
          "r"((b)[0]), "r"((b)[1]))

#define CP_ASYNC16(dst, src)                                                   \
    asm volatile("cp.async.cg.shared.global [%0], [%1], 16;"                   \
        :: "r"(dst), "l"(src) : "memory")
#define CP_COMMIT() asm volatile("cp.async.commit_group;" ::: "memory")
#define CP_WAIT(n)  asm volatile("cp.async.wait_group %0;" :: "n"(n) : "memory")

// ---------------------------------------------------------------------------
// mma.sync tf32 GEMM v2: 3-stage cp.async pipeline, RAW fp32 operands.
// The tf32 MMA truncates operands (R8-validated); the systematic ~7.0e-4
// downward bias of truncated products is cancelled in the epilogue via
// acc * 1.000704. One __syncthreads per stage; LDG latency covered by
// ~2 stages of MMA work. SPAD=20 scalar fragment loads (conflict-free, R4).
// ---------------------------------------------------------------------------
#define GPAD 20
#define GTILE (128 * GPAD)                 // words per tensor per stage
#define GSTG 3
#define GEMM_SMEM (GSTG * 2 * GTILE * 4)   // 61440 bytes

template<int RELU>
__global__ __launch_bounds__(256, 2)
void mma_gemm(const float* __restrict__ A, const float* __restrict__ W,
              const float* __restrict__ bias, float* __restrict__ C,
              int M, int N, int K)
{
    extern __shared__ float gsm[];

    const int tid  = threadIdx.x;
    const int wid  = tid >> 5, lane = tid & 31;
    const int grp  = lane >> 2, qd = lane & 3;
    const int wm   = (wid & 1) * 64;
    const int wn   = (wid >> 1) * 32;
    const int bm   = blockIdx.y * 128;
    const int bn   = blockIdx.x * 128;

    const int lrow = tid >> 1;             // 0..127
    const int lk8  = (tid & 1) * 8;        // 0 or 8

    const float* Ap = A + (size_t)(bm + lrow) * K + lk8;
    const float* Wp = W + (size_t)(bn + lrow) * K + lk8;

    uint32_t sAw[GSTG], sBw[GSTG];
    #pragma unroll
    for (int b = 0; b < GSTG; ++b) {
        sAw[b] = smem_u32(gsm + (2 * b    ) * GTILE + lrow * GPAD + lk8);
        sBw[b] = smem_u32(gsm + (2 * b + 1) * GTILE + lrow * GPAD + lk8);
    }

    const int NS = K >> 4;

    auto issue = [&](int s, int b) {
        const float* as = Ap + (size_t)s * 16;
        const float* ws = Wp + (size_t)s * 16;
        CP_ASYNC16(sAw[b],      as);
        CP_ASYNC16(sAw[b] + 16, as + 4);
        CP_ASYNC16(sBw[b],      ws);
        CP_ASYNC16(sBw[b] + 16, ws + 4);
    };

    issue(0, 0); CP_COMMIT();
    issue(1, 1); CP_COMMIT();

    float acc[4][4][4];
    #pragma unroll
    for (int i = 0; i < 4; i++)
        #pragma unroll
        for (int j = 0; j < 4; j++)
            #pragma unroll
            for (int r = 0; r < 4; r++) acc[i][j][r] = 0.f;

    for (int s = 0; s < NS; ++s) {
        CP_WAIT(1);                        // group for stage s complete
        __syncthreads();                   // all threads' data visible

        const int pb = s % GSTG;
        const float* Ab = gsm + (2 * pb    ) * GTILE;
        const float* Bb = gsm + (2 * pb + 1) * GTILE;

        #pragma unroll
        for (int ks = 0; ks < 2; ++ks) {
            const int kb = ks * 8;
            uint32_t af[4][4], bf[4][2];
            #pragma unroll
            for (int mt = 0; mt < 4; ++mt) {
                const int r = wm + mt * 16 + grp;
                af[mt][0] = __float_as_uint(Ab[(r    ) * GPAD + kb + qd]);
                af[mt][1] = __float_as_uint(Ab[(r + 8) * GPAD + kb + qd]);
                af[mt][2] = __float_as_uint(Ab[(r    ) * GPAD + kb + qd + 4]);
                af[mt][3] = __float_as_uint(Ab[(r + 8) * GPAD + kb + qd + 4]);
            }
            #pragma unroll
            for (int nt = 0; nt < 4; ++nt) {
                const int n = wn + nt * 8 + grp;
                bf[nt][0] = __float_as_uint(Bb[n * GPAD + kb + qd]);
                bf[nt][1] = __float_as_uint(Bb[n * GPAD + kb + qd + 4]);
            }
            #pragma unroll
            for (int mt = 0; mt < 4; ++mt)
                #pragma unroll
                for (int nt = 0; nt < 4; ++nt)
                    MMA_TF32(acc[mt][nt], af[mt], bf[nt]);
        }

        if (s + 2 < NS) issue(s + 2, (s + 2) % GSTG);
        CP_COMMIT();                       // unconditional: keeps group numbering
    }

    // epilogue: truncation-bias compensation + bias (+ReLU)
    const float COMP = 1.000704f;
    #pragma unroll
    for (int mt = 0; mt < 4; ++mt) {
        const int row = bm + wm + mt * 16 + grp;
        #pragma unroll
        for (int nt = 0; nt < 4; ++nt) {
            const int col = bn + wn + nt * 8 + 2 * qd;
            const float2 bv = *(const float2*)&bias[col];
            float2 o0, o1;
            o0.x = fmaf(acc[mt][nt][0], COMP, bv.x);
            o0.y = fmaf(acc[mt][nt][1], COMP, bv.y);
            o1.x = fmaf(acc[mt][nt][2], COMP, bv.x);
            o1.y = fmaf(acc[mt][nt][3], COMP, bv.y);
            if (RELU) {
                o0.x = fmaxf(o0.x, 0.f); o0.y = fmaxf(o0.y, 0.f);
                o1.x = fmaxf(o1.x, 0.f); o1.y = fmaxf(o1.y, 0.f);
            }
            *(float2*)(C + (size_t)row * N + col)       = o0;
            *(float2*)(C + (size_t)(row + 8) * N + col) = o1;
        }
    }
}

// ---------------------------------------------------------------------------
// mask tile flags (unchanged).
// ---------------------------------------------------------------------------
__global__ __launch_bounds__(256)
void mask_flags(const int* __restrict__ mask, int* __restrict__ flags)
{
    const int idx = blockIdx.x;
    const int qt = idx >> 5, st = idx & 31;
    const int tid = threadIdx.x;
    int ok = 1;
    for (int i = tid; i < 128 * 64; i += 256) {
        int r = qt * 128 + (i >> 6);
        int c = st * 64 + (i & 63);
        ok &= (mask[(size_t)r * LL + c] != 0);
    }
    int all = __syncthreads_and(ok);
    if (tid == 0) flags[idx] = all;
}

// ---------------------------------------------------------------------------
// Flash attention (R7-exact — the proven 893us configuration).
// ---------------------------------------------------------------------------
#define AST 72
#define ATT_SMEM ((128 * AST + 64 * AST + 64 * AST) * 4)   // 73728 B

__global__ __launch_bounds__(256)
void flash_attn_mma(const float* __restrict__ qkv, const int* __restrict__ mask,
                    const int* __restrict__ flags, float* __restrict__ vals)
{
    extern __shared__ float sm[];
    float* Qs = sm;                        // [128][AST], k-interleaved, scaled
    float* Ks = sm + 128 * AST;            // [64][AST],  k-interleaved
    float* Vs = Ks + 64 * AST;             // [64][AST],  normal layout

    const int tid  = threadIdx.x;
    const int wid  = tid >> 5, lane = tid & 31;
    const int grp  = lane >> 2, qd = lane & 3;
    const int qt   = blockIdx.x;
    const int head = blockIdx.y;
    const int b    = blockIdx.z;
    const int qbase = qt * 128;
    const int m0   = wid * 16;

    const float QSCALE = 0.125f * 1.44269504088896340736f;   // (1/8)*log2(e)

    const float* qp = qkv + ((size_t)(b * LL + qbase)) * (3 * DD) + head * (3 * HD);
    for (int s = tid; s < 128 * 16; s += 256) {
        int r = s >> 4, c = (s & 15) * 4;
        float4 v = *(const float4*)(qp + (size_t)r * (3 * DD) + c);
        const int kb = c & ~7, h = (c >> 2) & 1;
        uint32_t* row = (uint32_t*)&Qs[r * AST + kb + h];
        row[0] = f2tf32(v.x * QSCALE); row[2] = f2tf32(v.y * QSCALE);
        row[4] = f2tf32(v.z * QSCALE); row[6] = f2tf32(v.w * QSCALE);
    }

    float o[8][4];
    #pragma unroll
    for (int nt = 0; nt < 8; ++nt)
        #pragma unroll
        for (int r = 0; r < 4; ++r) o[nt][r] = 0.f;
    float m_0 = -INFINITY, m_1 = -INFINITY, l_0 = 0.f, l_1 = 0.f;

    for (int st = 0; st < LL / 64; ++st) {
        __syncthreads();
        const int sbase = st * 64;
        const float* kp = qkv + ((size_t)(b * LL + sbase)) * (3 * DD) + head * (3 * HD) + HD;
        for (int s = tid; s < 64 * 16; s += 256) {
            int r = s >> 4, c = (s & 15) * 4;
            float4 kv = *(const float4*)(kp + (size_t)r * (3 * DD) + c);
            float4 vv = *(const float4*)(kp + (size_t)r * (3 * DD) + HD + c);
            const int kb = c & ~7, h = (c >> 2) & 1;
            uint32_t* krow = (uint32_t*)&Ks[r * AST + kb + h];
            krow[0] = f2tf32(kv.x); krow[2] = f2tf32(kv.y);
            krow[4] = f2tf32(kv.z); krow[6] = f2tf32(kv.w);
            uint32_t* vrow = (uint32_t*)&Vs[r * AST + c];
            vrow[0] = f2tf32(vv.x); vrow[1] = f2tf32(vv.y);
            vrow[2] = f2tf32(vv.z); vrow[3] = f2tf32(vv.w);
        }
        __syncthreads();

        float sacc[8][4];
        #pragma unroll
        for (int nt = 0; nt < 8; ++nt)
            #pragma unroll
            for (int r = 0; r < 4; ++r) sacc[nt][r] = 0.f;

        #pragma unroll
        for (int ks = 0; ks < 8; ++ks) {
            const int k0 = ks * 8;
            uint32_t a[4];
            {
                uint2 a02 = *(const uint2*)&Qs[(m0 + grp    ) * AST + k0 + 2 * qd];
                uint2 a13 = *(const uint2*)&Qs[(m0 + grp + 8) * AST + k0 + 2 * qd];
                a[0] = a02.x; a[1] = a13.x; a[2] = a02.y; a[3] = a13.y;
            }
            #pragma unroll
            for (int nt = 0; nt < 8; ++nt) {
                uint2 b01 = *(const uint2*)&Ks[(nt * 8 + grp) * AST + k0 + 2 * qd];
                uint32_t bb[2] = { b01.x, b01.y };
                MMA_TF32(sacc[nt], a, bb);
            }
        }

        if (flags[qt * 32 + st] == 0) {
            const int r0g = qbase + m0 + grp, r1g = r0g + 8;
            #pragma unroll
            for (int nt = 0; nt < 8; ++nt) {
                const int c0 = sbase + nt * 8 + 2 * qd;
                if (mask[(size_t)r0g * LL + c0    ] == 0) sacc[nt][0] = -INFINITY;
                if (mask[(size_t)r0g * LL + c0 + 1] == 0) sacc[nt][1] = -INFINITY;
                if (mask[(size_t)r1g * LL + c0    ] == 0) sacc[nt][2] = -INFINITY;
                if (mask[(size_t)r1g * LL + c0 + 1] == 0) sacc[nt][3] = -INFINITY;
            }
        }

        float rm0 = -INFINITY, rm1 = -INFINITY;
        #pragma unroll
        for (int nt = 0; nt < 8; ++nt) {
            rm0 = fmaxf(rm0, fmaxf(sacc[nt][0], sacc[nt][1]));
            rm1 = fmaxf(rm1, fmaxf(sacc[nt][2], sacc[nt][3]));
        }
        rm0 = fmaxf(rm0, __shfl_xor_sync(0xffffffffu, rm0, 1));
        rm0 = fmaxf(rm0, __shfl_xor_sync(0xffffffffu, rm0, 2));
        rm1 = fmaxf(rm1, __shfl_xor_sync(0xffffffffu, rm1, 1));
        rm1 = fmaxf(rm1, __shfl_xor_sync(0xffffffffu, rm1, 2));
        const float mn0 = fmaxf(m_0, rm0), mn1 = fmaxf(m_1, rm1);
        const float al0 = exp2f(m_0 - mn0), al1 = exp2f(m_1 - mn1);
        m_0 = mn0; m_1 = mn1;

        float s0 = 0.f, s1 = 0.f;
        #pragma unroll
        for (int nt = 0; nt < 8; ++nt) {
            float p0 = __uint_as_float(f2tf32(exp2f(sacc[nt][0] - mn0)));
            float p1 = __uint_as_float(f2tf32(exp2f(sacc[nt][1] - mn0)));
            float p2 = __uint_as_float(f2tf32(exp2f(sacc[nt][2] - mn1)));
            float p3 = __uint_as_float(f2tf32(exp2f(sacc[nt][3] - mn1)));
            sacc[nt][0] = p0; sacc[nt][1] = p1; sacc[nt][2] = p2; sacc[nt][3] = p3;
            s0 += p0 + p1; s1 += p2 + p3;
        }
        s0 += __shfl_xor_sync(0xffffffffu, s0, 1);
        s0 += __shfl_xor_sync(0xffffffffu, s0, 2);
        s1 += __shfl_xor_sync(0xffffffffu, s1, 1);
        s1 += __shfl_xor_sync(0xffffffffu, s1, 2);
        l_0 = l_0 * al0 + s0;
        l_1 = l_1 * al1 + s1;
        #pragma unroll
        for (int nt = 0; nt < 8; ++nt) {
            o[nt][0] *= al0; o[nt][1] *= al0;
            o[nt][2] *= al1; o[nt][3] *= al1;
        }

        const int srl = (lane & ~3) | (qd >> 1);
        #pragma unroll
        for (int ks = 0; ks < 8; ++ks) {
            uint32_t a[4];
            {
                float t0 = __shfl_sync(0xffffffffu, sacc[ks][0], srl);
                float t1 = __shfl_sync(0xffffffffu, sacc[ks][1], srl);
                float u0 = __shfl_sync(0xffffffffu, sacc[ks][0], srl + 2);
                float u1 = __shfl_sync(0xffffffffu, sacc[ks][1], srl + 2);
                a[0] = __float_as_uint((qd & 1) ? t1 : t0);
                a[2] = __float_as_uint((qd & 1) ? u1 : u0);
                t0 = __shfl_sync(0xffffffffu, sacc[ks][2], srl);
                t1 = __shfl_sync(0xffffffffu, sacc[ks][3], srl);
                u0 = __shfl_sync(0xffffffffu, sacc[ks][2], srl + 2);
                u1 = __shfl_sync(0xffffffffu, sacc[ks][3], srl + 2);
                a[1] = __float_as_uint((qd & 1) ? t1 : t0);
                a[3] = __float_as_uint((qd & 1) ? u1 : u0);
            }
            const int k0 = ks * 8;
            #pragma unroll
            for (int nt = 0; nt < 8; ++nt) {
                uint32_t bb[2];
                bb[0] = __float_as_uint(Vs[(k0 + qd    ) * AST + nt * 8 + grp]);
                bb[1] = __float_as_uint(Vs[(k0 + qd + 4) * AST + nt * 8 + grp]);
                MMA_TF32(o[nt], a, bb);
            }
        }
    }

    const float li0 = 1.f / l_0, li1 = 1.f / l_1;
    const int r0g = qbase + m0 + grp;
    #pragma unroll
    for (int nt = 0; nt < 8; ++nt) {
        const int col = head * HD + nt * 8 + 2 * qd;
        float2 w0 = make_float2(o[nt][0] * li0, o[nt][1] * li0);
        float2 w1 = make_float2(o[nt][2] * li1, o[nt][3] * li1);
        *(float2*)&vals[((size_t)(b * LL + r0g    )) * DD + col] = w0;
        *(float2*)&vals[((size_t)(b * LL + r0g + 8)) * DD + col] = w1;
    }
}

// ---------------------------------------------------------------------------
// Fused residual-add + LayerNorm (unchanged).
// ---------------------------------------------------------------------------
__global__ __launch_bounds__(128)
void add_ln(const float* __restrict__ a, const float* __restrict__ bres,
            const float* __restrict__ g, const float* __restrict__ beta,
            float* __restrict__ out)
{
    const int row = blockIdx.x;
    const int tid = threadIdx.x;

    float4 av = ((const float4*)(a    + (size_t)row * DD))[tid];
    float4 bv = ((const float4*)(bres + (size_t)row * DD))[tid];
    float4 x = make_float4(av.x+bv.x, av.y+bv.y, av.z+bv.z, av.w+bv.w);

    float s  = x.x + x.y + x.z + x.w;
    float ss = x.x*x.x + x.y*x.y + x.z*x.z + x.w*x.w;

    #pragma unroll
    for (int o = 16; o > 0; o >>= 1) {
        s  += __shfl_xor_sync(0xffffffffu, s,  o);
        ss += __shfl_xor_sync(0xffffffffu, ss, o);
    }
    __shared__ float red[2][4];
    const int w = tid >> 5, l = tid & 31;
    if (l == 0) { red[0][w] = s; red[1][w] = ss; }
    __syncthreads();
    s  = red[0][0] + red[0][1] + red[0][2] + red[0][3];
    ss = red[1][0] + red[1][1] + red[1][2] + red[1][3];

    const float mean = s * (1.f / DD);
    const float var  = ss * (1.f / DD) - mean * mean;
    const float rstd = rsqrtf(var + 1e-5f);

    float4 gv = ((const float4*)g)[tid];
    float4 ev = ((const float4*)beta)[tid];
    float4 o;
    o.x = (x.x - mean) * rstd * gv.x + ev.x;
    o.y = (x.y - mean) * rstd * gv.y + ev.y;
    o.z = (x.z - mean) * rstd * gv.z + ev.z;
    o.w = (x.w - mean) * rstd * gv.w + ev.w;
    ((float4*)(out + (size_t)row * DD))[tid] = o;
}

// ---------------------------------------------------------------------------
extern "C" void kernel_launch(void* const* d_in, const int* in_sizes, int n_in,
                              void* d_out, int out_size)
{
    const float* src    = (const float*)d_in[0];
    const int*   mask   = (const int*)  d_in[1];
    const float* qkv_w  = (const float*)d_in[2];
    const float* qkv_b  = (const float*)d_in[3];
    const float* out_w  = (const float*)d_in[4];
    const float* out_b  = (const float*)d_in[5];
    const float* w1     = (const float*)d_in[6];
    const float* b1     = (const float*)d_in[7];
    const float* w2     = (const float*)d_in[8];
    const float* b2     = (const float*)d_in[9];
    const float* g1     = (const float*)d_in[10];
    const float* beta1  = (const float*)d_in[11];
    const float* g2     = (const float*)d_in[12];
    const float* beta2  = (const float*)d_in[13];
    float* out = (float*)d_out;

    void* p;
    cudaGetSymbolAddress(&p, g_qkv);   float* qkv   = (float*)p;
    cudaGetSymbolAddress(&p, g_vals);  float* vals  = (float*)p;
    cudaGetSymbolAddress(&p, g_tmp);   float* tmp   = (float*)p;
    cudaGetSymbolAddress(&p, g_x1);    float* x1    = (float*)p;
    cudaGetSymbolAddress(&p, g_ff);    float* ff    = (float*)p;
    cudaGetSymbolAddress(&p, g_mflag); int*   mflag = (int*)p;

    cudaFuncSetAttribute(mma_gemm<0>, cudaFuncAttributeMaxDynamicSharedMemorySize, GEMM_SMEM);
    cudaFuncSetAttribute(mma_gemm<1>, cudaFuncAttributeMaxDynamicSharedMemorySize, GEMM_SMEM);
    cudaFuncSetAttribute(flash_attn_mma, cudaFuncAttributeMaxDynamicSharedMemorySize, ATT_SMEM);

    // 0) mask tile flags
    mask_flags<<<512, 256>>>(mask, mflag);

    // 1) QKV projection
    mma_gemm<0><<<dim3((3*DD)/128, MR/128), 256, GEMM_SMEM>>>(src, qkv_w, qkv_b, qkv, MR, 3*DD, DD);

    // 2) flash attention
    flash_attn_mma<<<dim3(LL/128, HH, BB), 256, ATT_SMEM>>>(qkv, mask, mflag, vals);

    // 3) output projection
    mma_gemm<0><<<dim3(DD/128, MR/128), 256, GEMM_SMEM>>>(vals, out_w, out_b, tmp, MR, DD, DD);

    // 4) x1 = LN(src + proj)
    add_ln<<<MR, 128>>>(src, tmp, g1, beta1, x1);

    // 5) FFN1 + ReLU
    mma_gemm<1><<<dim3(DFF/128, MR/128), 256, GEMM_SMEM>>>(x1, w1, b1, ff, MR, DFF, DD);

    // 6) FFN2
    mma_gemm<0><<<dim3(DD/128, MR/128), 256, GEMM_SMEM>>>(ff, w2, b2, tmp, MR, DD, DFF);

    // 7) out = LN(x1 + ffn2)
    add_ln<<<MR, 128>>>(x1, tmp, g2, beta2, out);
}